// round 6
// baseline (speedup 1.0000x reference)
#include <cuda_runtime.h>
#include <cuda_bf16.h>
#include <math.h>

#define RR 3
#define TT 3
#define NN 50000
#define OPS 24
#define EE 400000
#define BB 32
#define MAXDEG 8
#define HH 128

// ---------------- device scratch (allocations are forbidden) ----------------
__device__ float4 g_Wpk[2 * 128 * 128];      // entity Whh packed [dir][k][j] -> (i,f,g,o)
__device__ float4 g_xpk[2 * 25 * 128];       // entity input projection table [dir][v][j]
__device__ float4 g_qWpk[6 * 128 * 128];     // query Whh packed [(r,dir)][k][j]
__device__ float4 g_qWihpk[6 * 128 * 128];   // query Wih packed [(r,dir)][k][j]
__device__ float4 g_qbpk[6 * 128];           // query bias packed (bih+bhh)
__device__ __align__(16) float g_eh[NN * 256];       // entity bilstm final hidden
__device__ float g_eattn[NN * 24];                   // entity attention
__device__ float g_qh[6 * 3 * BB * 128];             // query lstm hiddens [(r,dir)][t][b][j]
__device__ float g_qattn[3 * 25 * 96];               // [t][op][col], col = r*32+b
__device__ __align__(16) float g_mem[NN * 96];
__device__ __align__(16) float g_next[NN * 96];
__device__ float g_sums[96];

// ---------------- FMA-only activations (MUFU would be the bottleneck) -------
__device__ __forceinline__ float tanh_fast(float x) {
    float a = fabsf(x);
    if (a > 0.53f) return tanhf(x);   // rare guard; keeps correctness unconditional
    float s = x * x;
    float p = 2.1869489e-2f;          // 62/2835
    p = fmaf(p, s, -5.3968254e-2f);   // -17/315
    p = fmaf(p, s, 1.3333334e-1f);    // 2/15
    p = fmaf(p, s, -3.3333334e-1f);   // -1/3
    return fmaf(p * s, x, x);
}
__device__ __forceinline__ float sig_fast(float x) {
    return fmaf(tanh_fast(0.5f * x), 0.5f, 0.5f);
}
__device__ __forceinline__ void fma4(float4& a, float h, const float4 w) {
    a.x = fmaf(h, w.x, a.x);
    a.y = fmaf(h, w.y, a.y);
    a.z = fmaf(h, w.z, a.z);
    a.w = fmaf(h, w.w, a.w);
}

// ---------------- weight packing ----------------
__device__ __forceinline__ float4 pack_row(const float* __restrict__ W, int i) {
    int grp = i >> 14, k = (i >> 7) & 127, j = i & 127;
    const float* b = W + grp * 65536;
    return make_float4(b[j * 128 + k], b[(128 + j) * 128 + k],
                       b[(256 + j) * 128 + k], b[(384 + j) * 128 + k]);
}
__global__ void k_pack_ewhh(const float* __restrict__ W) {
    int i = blockIdx.x * 256 + threadIdx.x;
    if (i < 2 * 16384) g_Wpk[i] = pack_row(W, i);
}
__global__ void k_pack_qwhh(const float* __restrict__ W) {
    int i = blockIdx.x * 256 + threadIdx.x;
    if (i < 6 * 16384) g_qWpk[i] = pack_row(W, i);
}
__global__ void k_pack_qwih(const float* __restrict__ W) {
    int i = blockIdx.x * 256 + threadIdx.x;
    if (i < 6 * 16384) g_qWihpk[i] = pack_row(W, i);
}
__global__ void k_pack_qb(const float* __restrict__ bih, const float* __restrict__ bhh) {
    int i = blockIdx.x * 256 + threadIdx.x;
    if (i >= 6 * 128) return;
    int rd = i >> 7, j = i & 127;
    const float* b1 = bih + rd * 512;
    const float* b2 = bhh + rd * 512;
    g_qbpk[i] = make_float4(b1[j] + b2[j], b1[128 + j] + b2[128 + j],
                            b1[256 + j] + b2[256 + j], b1[384 + j] + b2[384 + j]);
}
// entity input projection table: only 25 distinct degree values exist
__global__ void k_pack_exp(const float* __restrict__ emb, const float* __restrict__ Wih,
                           const float* __restrict__ bih, const float* __restrict__ bhh) {
    int i = blockIdx.x * 256 + threadIdx.x;
    if (i >= 2 * 25 * 128) return;
    int dir = i / 3200, rest = i - dir * 3200, v = rest >> 7, j = rest & 127;
    float4 r;
    float* rp = (float*)&r;
#pragma unroll
    for (int g = 0; g < 4; g++) {
        int row = g * 128 + j;
        float a = bih[dir * 512 + row] + bhh[dir * 512 + row];
        const float* wr = Wih + (dir * 512 + row) * 128;
        const float* ev = emb + v * 128;
#pragma unroll 8
        for (int k = 0; k < 128; k++) a = fmaf(ev[k], wr[k], a);
        rp[g] = a;
    }
    g_xpk[i] = r;
}

// ---------------- entity BiLSTM: the FLOP giant ----------------
// blockDim 256: tx in [0,32) covers j = tx + 32*jj ; ty in [0,8) covers rows m0 = 4*ty.
__global__ void __launch_bounds__(256) k_elstm(const int* __restrict__ deg) {
    int dir = blockIdx.y;
    int n0 = blockIdx.x * 32;
    int tid = threadIdx.x;
    int tx = tid & 31, ty = tid >> 5, m0 = ty * 4;
    __shared__ float hs[32][128];
    __shared__ int degs[32][MAXDEG];
    {
        int m = tid >> 3, s2 = tid & 7;
        int n = n0 + m;
        degs[m][s2] = (n < NN) ? __ldg(&deg[n * MAXDEG + s2]) : 0;
    }
    __syncthreads();
    const float4* __restrict__ Wpk = g_Wpk + dir * 16384;
    const float4* __restrict__ xpk = g_xpk + dir * 3200;
    float c[4][4];
    float4 acc[4][4];
#pragma unroll
    for (int mm = 0; mm < 4; mm++)
#pragma unroll
        for (int jj = 0; jj < 4; jj++) c[mm][jj] = 0.f;

    for (int s = 0; s < MAXDEG; s++) {
#pragma unroll
        for (int mm = 0; mm < 4; mm++) {
            int v = degs[m0 + mm][dir ? (7 - s) : s];
#pragma unroll
            for (int jj = 0; jj < 4; jj++) acc[mm][jj] = xpk[v * 128 + tx + 32 * jj];
        }
        if (s > 0) {
#pragma unroll 4
            for (int k = 0; k < 128; k++) {
                float4 w0 = Wpk[k * 128 + tx];
                float4 w1 = Wpk[k * 128 + tx + 32];
                float4 w2 = Wpk[k * 128 + tx + 64];
                float4 w3 = Wpk[k * 128 + tx + 96];
#pragma unroll
                for (int mm = 0; mm < 4; mm++) {
                    float h = hs[m0 + mm][k];
                    fma4(acc[mm][0], h, w0);
                    fma4(acc[mm][1], h, w1);
                    fma4(acc[mm][2], h, w2);
                    fma4(acc[mm][3], h, w3);
                }
            }
        }
        __syncthreads();   // all reads of old h done
#pragma unroll
        for (int mm = 0; mm < 4; mm++)
#pragma unroll
            for (int jj = 0; jj < 4; jj++) {
                float4 a = acc[mm][jj];
                float iv = sig_fast(a.x), fv = sig_fast(a.y);
                float gv = tanh_fast(a.z), ov = sig_fast(a.w);
                float cn = fmaf(fv, c[mm][jj], iv * gv);
                c[mm][jj] = cn;
                hs[m0 + mm][tx + 32 * jj] = ov * tanh_fast(cn);
            }
        __syncthreads();   // new h visible
    }
#pragma unroll
    for (int mm = 0; mm < 4; mm++) {
        int n = n0 + m0 + mm;
        if (n < NN) {
#pragma unroll
            for (int jj = 0; jj < 4; jj++)
                g_eh[n * 256 + dir * 128 + tx + 32 * jj] = hs[m0 + mm][tx + 32 * jj];
        }
    }
}

// ---------------- entity attention: softmax(e_h @ W.T + b), warp per entity --
__global__ void __launch_bounds__(256) k_eattn(const float* __restrict__ W,
                                               const float* __restrict__ bias) {
    int tid = threadIdx.x, lane = tid & 31, wy = tid >> 5;
    int n = blockIdx.x * 8 + wy;
    __shared__ float z[8][24];
    if (n >= NN) return;
    float eh[8];
#pragma unroll
    for (int i = 0; i < 8; i++) eh[i] = g_eh[n * 256 + lane + 32 * i];
    for (int o = 0; o < 24; o++) {
        float acc = 0.f;
#pragma unroll
        for (int i = 0; i < 8; i++) acc = fmaf(eh[i], __ldg(&W[o * 256 + lane + 32 * i]), acc);
#pragma unroll
        for (int off = 16; off; off >>= 1) acc += __shfl_xor_sync(0xffffffffu, acc, off);
        if (lane == 0) z[wy][o] = acc + bias[o];
    }
    __syncwarp();
    if (lane < 24) {
        float mx = -1e30f;
#pragma unroll
        for (int o = 0; o < 24; o++) mx = fmaxf(mx, z[wy][o]);
        float sm = 0.f;
#pragma unroll
        for (int o = 0; o < 24; o++) sm += expf(z[wy][o] - mx);
        g_eattn[n * 24 + lane] = expf(z[wy][lane] - mx) / sm;
    }
}

// ---------------- query BiLSTM (tiny; input constant across time) -----------
__global__ void __launch_bounds__(256) k_qlstm(const int* __restrict__ queries,
                                               const float* __restrict__ qemb) {
    int rd = blockIdx.x;  // r*2 + dir
    int tid = threadIdx.x;
    int tx = tid & 31, ty = tid >> 5, m0 = ty * 4;
    __shared__ float xs[32][128];
    __shared__ float hs[32][128];
    for (int i = tid; i < 32 * 128; i += 256) {
        int m = i >> 7, k = i & 127;
        xs[m][k] = qemb[queries[m] * 128 + k];
    }
    __syncthreads();
    const float4* __restrict__ Wih = g_qWihpk + rd * 16384;
    const float4* __restrict__ Wpk = g_qWpk + rd * 16384;
    const float4* __restrict__ bpk = g_qbpk + rd * 128;
    float4 xp[4][4];
#pragma unroll
    for (int mm = 0; mm < 4; mm++)
#pragma unroll
        for (int jj = 0; jj < 4; jj++) xp[mm][jj] = bpk[tx + 32 * jj];
#pragma unroll 4
    for (int k = 0; k < 128; k++) {
        float4 w0 = Wih[k * 128 + tx];
        float4 w1 = Wih[k * 128 + tx + 32];
        float4 w2 = Wih[k * 128 + tx + 64];
        float4 w3 = Wih[k * 128 + tx + 96];
#pragma unroll
        for (int mm = 0; mm < 4; mm++) {
            float x = xs[m0 + mm][k];
            fma4(xp[mm][0], x, w0);
            fma4(xp[mm][1], x, w1);
            fma4(xp[mm][2], x, w2);
            fma4(xp[mm][3], x, w3);
        }
    }
    float c[4][4];
#pragma unroll
    for (int mm = 0; mm < 4; mm++)
#pragma unroll
        for (int jj = 0; jj < 4; jj++) c[mm][jj] = 0.f;
    for (int t = 0; t < 3; t++) {
        float4 acc[4][4];
#pragma unroll
        for (int mm = 0; mm < 4; mm++)
#pragma unroll
            for (int jj = 0; jj < 4; jj++) acc[mm][jj] = xp[mm][jj];
        if (t > 0) {
#pragma unroll 4
            for (int k = 0; k < 128; k++) {
                float4 w0 = Wpk[k * 128 + tx];
                float4 w1 = Wpk[k * 128 + tx + 32];
                float4 w2 = Wpk[k * 128 + tx + 64];
                float4 w3 = Wpk[k * 128 + tx + 96];
#pragma unroll
                for (int mm = 0; mm < 4; mm++) {
                    float h = hs[m0 + mm][k];
                    fma4(acc[mm][0], h, w0);
                    fma4(acc[mm][1], h, w1);
                    fma4(acc[mm][2], h, w2);
                    fma4(acc[mm][3], h, w3);
                }
            }
        }
        __syncthreads();
#pragma unroll
        for (int mm = 0; mm < 4; mm++)
#pragma unroll
            for (int jj = 0; jj < 4; jj++) {
                float4 a = acc[mm][jj];
                float iv = sig_fast(a.x), fv = sig_fast(a.y);
                float gv = tanh_fast(a.z), ov = sig_fast(a.w);
                float cn = fmaf(fv, c[mm][jj], iv * gv);
                c[mm][jj] = cn;
                float hv = ov * tanh_fast(cn);
                hs[m0 + mm][tx + 32 * jj] = hv;
                g_qh[rd * 12288 + t * 4096 + (m0 + mm) * 128 + tx + 32 * jj] = hv;
            }
        __syncthreads();
    }
}

// ---------------- query attention: softmax over 25 ops, warp per (r,t,b) ----
__global__ void __launch_bounds__(256) k_qattn(const float* __restrict__ W,
                                               const float* __restrict__ bias) {
    int tid = threadIdx.x, lane = tid & 31, wy = tid >> 5;
    int w = blockIdx.x * 8 + wy;
    __shared__ float z[8][25];
    if (w >= 288) return;
    int r = w / 96, rem = w - r * 96, t = rem >> 5, b = rem & 31;
    float ys[8];
#pragma unroll
    for (int i = 0; i < 4; i++) ys[i] = g_qh[(2 * r) * 12288 + t * 4096 + b * 128 + lane + 32 * i];
#pragma unroll
    for (int i = 4; i < 8; i++) ys[i] = g_qh[(2 * r + 1) * 12288 + (2 - t) * 4096 + b * 128 + lane + 32 * (i - 4)];
    for (int o = 0; o < 25; o++) {
        float acc = 0.f;
#pragma unroll
        for (int i = 0; i < 8; i++) acc = fmaf(ys[i], __ldg(&W[o * 256 + lane + 32 * i]), acc);
#pragma unroll
        for (int off = 16; off; off >>= 1) acc += __shfl_xor_sync(0xffffffffu, acc, off);
        if (lane == 0) z[wy][o] = acc + bias[o];
    }
    __syncwarp();
    if (lane < 25) {
        float mx = -1e30f;
#pragma unroll
        for (int o = 0; o < 25; o++) mx = fmaxf(mx, z[wy][o]);
        float sm = 0.f;
#pragma unroll
        for (int o = 0; o < 25; o++) sm += expf(z[wy][o] - mx);
        g_qattn[t * 2400 + lane * 96 + r * 32 + b] = expf(z[wy][lane] - mx) / sm;
    }
}

// ---------------- propagation (R,B fused into 96 lanes) ----------------
__global__ void k_zero_state() {
    int i = blockIdx.x * 256 + threadIdx.x;
    if (i < NN * 24) {
        ((float4*)g_mem)[i] = make_float4(0.f, 0.f, 0.f, 0.f);
        ((float4*)g_next)[i] = make_float4(0.f, 0.f, 0.f, 0.f);
    }
}
__global__ void k_set_heads(const int* __restrict__ heads) {
    int i = threadIdx.x;  // 96
    if (i < 96) g_mem[heads[i & 31] * 96 + i] = 1.0f;
}
__global__ void k_zero_sums() {
    if (threadIdx.x < 96) g_sums[threadIdx.x] = 0.f;
}
// thread handles one (edge, quad-of-4-cols); atomics predicated on nonzero memory
__global__ void __launch_bounds__(256) k_scatter(const int* __restrict__ rels,
                                                 const int* __restrict__ th,
                                                 const int* __restrict__ tt, int tstep) {
    __shared__ float qs[25 * 96];
    for (int i = threadIdx.x; i < 2400; i += 256) qs[i] = g_qattn[tstep * 2400 + i];
    __syncthreads();
    int i = blockIdx.x * 256 + threadIdx.x;  // exactly E*24 threads
    int e = i / 24, q = i - e * 24, c0 = q * 4;
    int h = __ldg(&th[e]), t_ = __ldg(&tt[e]);
    float4 mh = *reinterpret_cast<const float4*>(&g_mem[h * 96 + c0]);
    float4 mt = *reinterpret_cast<const float4*>(&g_mem[t_ * 96 + c0]);
    // one-hot start => vast majority of edges see all-zero memory on both ends
    bool any_h = (mh.x != 0.f) | (mh.y != 0.f) | (mh.z != 0.f) | (mh.w != 0.f);
    bool any_t = (mt.x != 0.f) | (mt.y != 0.f) | (mt.z != 0.f) | (mt.w != 0.f);
    if (!(any_h | any_t)) return;
    int rel = __ldg(&rels[e]);
    float wv = __ldg(&g_eattn[h * 24 + rel]);
    const float* qf = qs + rel * 96 + c0;
    const float* qr = qs + (rel + 12) * 96 + c0;
    float* nt = g_next + t_ * 96 + c0;
    float* nh = g_next + h * 96 + c0;
    if (mh.x != 0.f) atomicAdd(nt + 0, qf[0] * wv * mh.x);
    if (mh.y != 0.f) atomicAdd(nt + 1, qf[1] * wv * mh.y);
    if (mh.z != 0.f) atomicAdd(nt + 2, qf[2] * wv * mh.z);
    if (mh.w != 0.f) atomicAdd(nt + 3, qf[3] * wv * mh.w);
    if (mt.x != 0.f) atomicAdd(nh + 0, qr[0] * wv * mt.x);
    if (mt.y != 0.f) atomicAdd(nh + 1, qr[1] * wv * mt.y);
    if (mt.z != 0.f) atomicAdd(nh + 2, qr[2] * wv * mt.z);
    if (mt.w != 0.f) atomicAdd(nh + 3, qr[3] * wv * mt.w);
}
// add self term, accumulate per-column sums (one atomic per thread)
__global__ void k_selfsum(int tstep) {
    int col = threadIdx.x;  // 96
    float qself = g_qattn[tstep * 2400 + 24 * 96 + col];
    int nbase = blockIdx.x * 64;
    float acc = 0.f;
    for (int r2 = 0; r2 < 64; r2++) {
        int n = nbase + r2;
        if (n < NN) {
            int idx = n * 96 + col;
            float v = g_next[idx] + g_mem[idx] * qself;
            g_next[idx] = v;
            acc += v;
        }
    }
    atomicAdd(&g_sums[col], acc);
}
__global__ void k_norm() {
    __shared__ float rs[96];
    if (threadIdx.x < 96) rs[threadIdx.x] = 1.0f / fmaxf(1e-20f, g_sums[threadIdx.x]);
    __syncthreads();
    int i = blockIdx.x * 256 + threadIdx.x;
    if (i >= NN * 96) return;
    int col = i % 96;
    g_mem[i] = g_next[i] * rs[col];
    g_next[i] = 0.f;
}
__global__ void k_final(float* __restrict__ out) {
    int i = blockIdx.x * 256 + threadIdx.x;
    if (i >= BB * NN) return;
    int b = i / NN, n = i - b * NN;
    out[i] = g_mem[n * 96 + b] + g_mem[n * 96 + 32 + b] + g_mem[n * 96 + 64 + b];
}

// ---------------- launcher ----------------
extern "C" void kernel_launch(void* const* d_in, const int* in_sizes, int n_in,
                              void* d_out, int out_size) {
    const int* queries = (const int*)d_in[0];
    const int* heads = (const int*)d_in[1];
    const int* rels = (const int*)d_in[2];
    const int* t_heads = (const int*)d_in[3];
    const int* t_tails = (const int*)d_in[4];
    const int* deg = (const int*)d_in[5];
    const float* qemb = (const float*)d_in[6];
    const float* eemb = (const float*)d_in[7];
    const float* q_Wih = (const float*)d_in[8];
    const float* q_Whh = (const float*)d_in[9];
    const float* q_bih = (const float*)d_in[10];
    const float* q_bhh = (const float*)d_in[11];
    const float* e_Wih = (const float*)d_in[12];
    const float* e_Whh = (const float*)d_in[13];
    const float* e_bih = (const float*)d_in[14];
    const float* e_bhh = (const float*)d_in[15];
    const float* q_lin_W = (const float*)d_in[16];
    const float* q_lin_b = (const float*)d_in[17];
    const float* e_lin_W = (const float*)d_in[18];
    const float* e_lin_b = (const float*)d_in[19];
    float* out = (float*)d_out;

    // pack weights
    k_pack_ewhh<<<(2 * 16384 + 255) / 256, 256>>>(e_Whh);
    k_pack_exp<<<(2 * 25 * 128 + 255) / 256, 256>>>(eemb, e_Wih, e_bih, e_bhh);
    k_pack_qwhh<<<(6 * 16384 + 255) / 256, 256>>>(q_Whh);
    k_pack_qwih<<<(6 * 16384 + 255) / 256, 256>>>(q_Wih);
    k_pack_qb<<<3, 256>>>(q_bih, q_bhh);

    // entity path
    k_elstm<<<dim3((NN + 31) / 32, 2), 256>>>(deg);
    k_eattn<<<(NN + 7) / 8, 256>>>(e_lin_W, e_lin_b);

    // query path
    k_qlstm<<<6, 256>>>(queries, qemb);
    k_qattn<<<36, 256>>>(q_lin_W, q_lin_b);

    // propagation: R and B fused into 96 columns, T=3 passes
    k_zero_state<<<(NN * 24 + 255) / 256, 256>>>();
    k_set_heads<<<1, 96>>>(heads);
    for (int t = 0; t < 3; t++) {
        k_zero_sums<<<1, 96>>>();
        k_scatter<<<(EE * 24) / 256, 256>>>(rels, t_heads, t_tails, t);
        k_selfsum<<<(NN + 63) / 64, 96>>>(t);
        k_norm<<<(NN * 96 + 255) / 256, 256>>>();
    }
    k_final<<<(BB * NN + 255) / 256, 256>>>(out);
}

// round 10
// speedup vs baseline: 1.1461x; 1.1461x over previous
#include <cuda_runtime.h>
#include <cuda_bf16.h>
#include <math.h>

#define RR 3
#define TT 3
#define NN 50000
#define OPS 24
#define EE 400000
#define BB 32
#define MAXDEG 8
#define HH 128

// ---------------- device scratch (allocations are forbidden) ----------------
__device__ float4 g_Wpk[2 * 128 * 128];      // entity Whh packed [dir][k][j] -> (i,f,g,o)
__device__ float4 g_xpk[2 * 25 * 128];       // entity input projection table [dir][v][j]
__device__ float4 g_qWpk[6 * 128 * 128];     // query Whh packed [(r,dir)][k][j]
__device__ float4 g_qWihpk[6 * 128 * 128];   // query Wih packed [(r,dir)][k][j]
__device__ float4 g_qbpk[6 * 128];           // query bias packed (bih+bhh)
__device__ __align__(16) float g_eh[NN * 256];       // entity bilstm final hidden
__device__ float g_eattn[NN * 24];                   // entity attention
__device__ float g_qh[6 * 3 * BB * 128];             // query lstm hiddens [(r,dir)][t][b][j]
__device__ float g_qattn[3 * 25 * 96];               // [t][op][col], col = r*32+b
__device__ __align__(16) float g_mem[NN * 96];
__device__ __align__(16) float g_next[NN * 96];
__device__ float g_sums[96];

// ---------------- FMA-only activations (MUFU would be the bottleneck) -------
__device__ __forceinline__ float tanh_fast(float x) {
    float a = fabsf(x);
    if (a > 0.53f) return tanhf(x);   // rare guard; keeps correctness unconditional
    float s = x * x;
    float p = 2.1869489e-2f;          // 62/2835
    p = fmaf(p, s, -5.3968254e-2f);   // -17/315
    p = fmaf(p, s, 1.3333334e-1f);    // 2/15
    p = fmaf(p, s, -3.3333334e-1f);   // -1/3
    return fmaf(p * s, x, x);
}
__device__ __forceinline__ float sig_fast(float x) {
    return fmaf(tanh_fast(0.5f * x), 0.5f, 0.5f);
}
__device__ __forceinline__ void fma4(float4& a, float h, const float4 w) {
    a.x = fmaf(h, w.x, a.x);
    a.y = fmaf(h, w.y, a.y);
    a.z = fmaf(h, w.z, a.z);
    a.w = fmaf(h, w.w, a.w);
}

// ---------------- packed fp32x2 FMA (FFMA2; ptxas never emits this itself) --
__device__ __forceinline__ void fma2(unsigned long long& d, unsigned long long a,
                                     unsigned long long b) {
    asm("fma.rn.f32x2 %0, %1, %2, %0;" : "+l"(d) : "l"(a), "l"(b));
}
__device__ __forceinline__ unsigned long long dup2(float h) {
    unsigned long long r;
    asm("mov.b64 %0, {%1, %1};" : "=l"(r) : "f"(h));
    return r;
}

// ---------------- weight packing ----------------
__device__ __forceinline__ float4 pack_row(const float* __restrict__ W, int i) {
    int grp = i >> 14, k = (i >> 7) & 127, j = i & 127;
    const float* b = W + grp * 65536;
    return make_float4(b[j * 128 + k], b[(128 + j) * 128 + k],
                       b[(256 + j) * 128 + k], b[(384 + j) * 128 + k]);
}
__global__ void k_pack_ewhh(const float* __restrict__ W) {
    int i = blockIdx.x * 256 + threadIdx.x;
    if (i < 2 * 16384) g_Wpk[i] = pack_row(W, i);
}
// fused query-side packing: Wih | Whh | bias
__global__ void k_pack_q(const float* __restrict__ Wih, const float* __restrict__ Whh,
                         const float* __restrict__ bih, const float* __restrict__ bhh) {
    int i = blockIdx.x * 256 + threadIdx.x;
    if (i < 6 * 16384) {
        g_qWihpk[i] = pack_row(Wih, i);
    } else if (i < 12 * 16384) {
        g_qWpk[i - 6 * 16384] = pack_row(Whh, i - 6 * 16384);
    } else if (i < 12 * 16384 + 768) {
        int ii = i - 12 * 16384;
        int rd = ii >> 7, j = ii & 127;
        const float* b1 = bih + rd * 512;
        const float* b2 = bhh + rd * 512;
        g_qbpk[ii] = make_float4(b1[j] + b2[j], b1[128 + j] + b2[128 + j],
                                 b1[256 + j] + b2[256 + j], b1[384 + j] + b2[384 + j]);
    }
}
// entity input projection table: only 25 distinct degree values exist
__global__ void k_pack_exp(const float* __restrict__ emb, const float* __restrict__ Wih,
                           const float* __restrict__ bih, const float* __restrict__ bhh) {
    int i = blockIdx.x * 256 + threadIdx.x;
    if (i >= 2 * 25 * 128) return;
    int dir = i / 3200, rest = i - dir * 3200, v = rest >> 7, j = rest & 127;
    float4 r;
    float* rp = (float*)&r;
#pragma unroll
    for (int g = 0; g < 4; g++) {
        int row = g * 128 + j;
        float a = bih[dir * 512 + row] + bhh[dir * 512 + row];
        const float* wr = Wih + (dir * 512 + row) * 128;
        const float* ev = emb + v * 128;
#pragma unroll 8
        for (int k = 0; k < 128; k++) a = fmaf(ev[k], wr[k], a);
        rp[g] = a;
    }
    g_xpk[i] = r;
}

// ---------------- entity BiLSTM: the FLOP giant (FFMA2 inner loop) ----------
// blockDim 256: tx in [0,32) covers j = tx + 32*jj ; ty in [0,8) covers rows m0 = 4*ty.
__global__ void __launch_bounds__(256) k_elstm(const int* __restrict__ deg) {
    int dir = blockIdx.y;
    int n0 = blockIdx.x * 32;
    int tid = threadIdx.x;
    int tx = tid & 31, ty = tid >> 5, m0 = ty * 4;
    __shared__ float hs[32][128];
    __shared__ int degs[32][MAXDEG];
    {
        int m = tid >> 3, s2 = tid & 7;
        int n = n0 + m;
        degs[m][s2] = (n < NN) ? __ldg(&deg[n * MAXDEG + s2]) : 0;
    }
    __syncthreads();
    const ulonglong2* __restrict__ Wp2 =
        reinterpret_cast<const ulonglong2*>(g_Wpk + dir * 16384);
    const ulonglong2* __restrict__ xp2 =
        reinterpret_cast<const ulonglong2*>(g_xpk + dir * 3200);
    float c[4][4];
    ulonglong2 acc[4][4];   // packed gate pairs: .x=(i,f), .y=(g,o)
#pragma unroll
    for (int mm = 0; mm < 4; mm++)
#pragma unroll
        for (int jj = 0; jj < 4; jj++) c[mm][jj] = 0.f;

    for (int s = 0; s < MAXDEG; s++) {
#pragma unroll
        for (int mm = 0; mm < 4; mm++) {
            int v = degs[m0 + mm][dir ? (7 - s) : s];
#pragma unroll
            for (int jj = 0; jj < 4; jj++) acc[mm][jj] = xp2[v * 128 + tx + 32 * jj];
        }
        if (s > 0) {
#pragma unroll 4
            for (int k = 0; k < 128; k++) {
                ulonglong2 w0 = Wp2[k * 128 + tx];
                ulonglong2 w1 = Wp2[k * 128 + tx + 32];
                ulonglong2 w2 = Wp2[k * 128 + tx + 64];
                ulonglong2 w3 = Wp2[k * 128 + tx + 96];
#pragma unroll
                for (int mm = 0; mm < 4; mm++) {
                    unsigned long long h2 = dup2(hs[m0 + mm][k]);
                    fma2(acc[mm][0].x, h2, w0.x);
                    fma2(acc[mm][0].y, h2, w0.y);
                    fma2(acc[mm][1].x, h2, w1.x);
                    fma2(acc[mm][1].y, h2, w1.y);
                    fma2(acc[mm][2].x, h2, w2.x);
                    fma2(acc[mm][2].y, h2, w2.y);
                    fma2(acc[mm][3].x, h2, w3.x);
                    fma2(acc[mm][3].y, h2, w3.y);
                }
            }
        }
        __syncthreads();   // all reads of old h done
#pragma unroll
        for (int mm = 0; mm < 4; mm++)
#pragma unroll
            for (int jj = 0; jj < 4; jj++) {
                float4 a = *reinterpret_cast<float4*>(&acc[mm][jj]);
                float iv = sig_fast(a.x), fv = sig_fast(a.y);
                float gv = tanh_fast(a.z), ov = sig_fast(a.w);
                float cn = fmaf(fv, c[mm][jj], iv * gv);
                c[mm][jj] = cn;
                hs[m0 + mm][tx + 32 * jj] = ov * tanh_fast(cn);
            }
        __syncthreads();   // new h visible
    }
#pragma unroll
    for (int mm = 0; mm < 4; mm++) {
        int n = n0 + m0 + mm;
        if (n < NN) {
#pragma unroll
            for (int jj = 0; jj < 4; jj++)
                g_eh[n * 256 + dir * 128 + tx + 32 * jj] = hs[m0 + mm][tx + 32 * jj];
        }
    }
}

// ---------------- entity attention: softmax(e_h @ W.T + b), warp per entity --
__global__ void __launch_bounds__(256) k_eattn(const float* __restrict__ W,
                                               const float* __restrict__ bias) {
    int tid = threadIdx.x, lane = tid & 31, wy = tid >> 5;
    int n = blockIdx.x * 8 + wy;
    __shared__ float z[8][24];
    if (n >= NN) return;
    float eh[8];
#pragma unroll
    for (int i = 0; i < 8; i++) eh[i] = g_eh[n * 256 + lane + 32 * i];
    for (int o = 0; o < 24; o++) {
        float acc = 0.f;
#pragma unroll
        for (int i = 0; i < 8; i++) acc = fmaf(eh[i], __ldg(&W[o * 256 + lane + 32 * i]), acc);
#pragma unroll
        for (int off = 16; off; off >>= 1) acc += __shfl_xor_sync(0xffffffffu, acc, off);
        if (lane == 0) z[wy][o] = acc + bias[o];
    }
    __syncwarp();
    if (lane < 24) {
        float mx = -1e30f;
#pragma unroll
        for (int o = 0; o < 24; o++) mx = fmaxf(mx, z[wy][o]);
        float sm = 0.f;
#pragma unroll
        for (int o = 0; o < 24; o++) sm += expf(z[wy][o] - mx);
        g_eattn[n * 24 + lane] = expf(z[wy][lane] - mx) / sm;
    }
}

// ---------------- query BiLSTM (tiny; input constant across time) -----------
__global__ void __launch_bounds__(256) k_qlstm(const int* __restrict__ queries,
                                               const float* __restrict__ qemb) {
    int rd = blockIdx.x;  // r*2 + dir
    int tid = threadIdx.x;
    int tx = tid & 31, ty = tid >> 5, m0 = ty * 4;
    __shared__ float xs[32][128];
    __shared__ float hs[32][128];
    for (int i = tid; i < 32 * 128; i += 256) {
        int m = i >> 7, k = i & 127;
        xs[m][k] = qemb[queries[m] * 128 + k];
    }
    __syncthreads();
    const float4* __restrict__ Wih = g_qWihpk + rd * 16384;
    const float4* __restrict__ Wpk = g_qWpk + rd * 16384;
    const float4* __restrict__ bpk = g_qbpk + rd * 128;
    float4 xp[4][4];
#pragma unroll
    for (int mm = 0; mm < 4; mm++)
#pragma unroll
        for (int jj = 0; jj < 4; jj++) xp[mm][jj] = bpk[tx + 32 * jj];
#pragma unroll 4
    for (int k = 0; k < 128; k++) {
        float4 w0 = Wih[k * 128 + tx];
        float4 w1 = Wih[k * 128 + tx + 32];
        float4 w2 = Wih[k * 128 + tx + 64];
        float4 w3 = Wih[k * 128 + tx + 96];
#pragma unroll
        for (int mm = 0; mm < 4; mm++) {
            float x = xs[m0 + mm][k];
            fma4(xp[mm][0], x, w0);
            fma4(xp[mm][1], x, w1);
            fma4(xp[mm][2], x, w2);
            fma4(xp[mm][3], x, w3);
        }
    }
    float c[4][4];
#pragma unroll
    for (int mm = 0; mm < 4; mm++)
#pragma unroll
        for (int jj = 0; jj < 4; jj++) c[mm][jj] = 0.f;
    for (int t = 0; t < 3; t++) {
        float4 acc[4][4];
#pragma unroll
        for (int mm = 0; mm < 4; mm++)
#pragma unroll
            for (int jj = 0; jj < 4; jj++) acc[mm][jj] = xp[mm][jj];
        if (t > 0) {
#pragma unroll 4
            for (int k = 0; k < 128; k++) {
                float4 w0 = Wpk[k * 128 + tx];
                float4 w1 = Wpk[k * 128 + tx + 32];
                float4 w2 = Wpk[k * 128 + tx + 64];
                float4 w3 = Wpk[k * 128 + tx + 96];
#pragma unroll
                for (int mm = 0; mm < 4; mm++) {
                    float h = hs[m0 + mm][k];
                    fma4(acc[mm][0], h, w0);
                    fma4(acc[mm][1], h, w1);
                    fma4(acc[mm][2], h, w2);
                    fma4(acc[mm][3], h, w3);
                }
            }
        }
        __syncthreads();
#pragma unroll
        for (int mm = 0; mm < 4; mm++)
#pragma unroll
            for (int jj = 0; jj < 4; jj++) {
                float4 a = acc[mm][jj];
                float iv = sig_fast(a.x), fv = sig_fast(a.y);
                float gv = tanh_fast(a.z), ov = sig_fast(a.w);
                float cn = fmaf(fv, c[mm][jj], iv * gv);
                c[mm][jj] = cn;
                float hv = ov * tanh_fast(cn);
                hs[m0 + mm][tx + 32 * jj] = hv;
                g_qh[rd * 12288 + t * 4096 + (m0 + mm) * 128 + tx + 32 * jj] = hv;
            }
        __syncthreads();
    }
}

// ---------------- query attention: softmax over 25 ops, warp per (r,t,b) ----
__global__ void __launch_bounds__(256) k_qattn(const float* __restrict__ W,
                                               const float* __restrict__ bias) {
    int tid = threadIdx.x, lane = tid & 31, wy = tid >> 5;
    int w = blockIdx.x * 8 + wy;
    __shared__ float z[8][25];
    if (w >= 288) return;
    int r = w / 96, rem = w - r * 96, t = rem >> 5, b = rem & 31;
    float ys[8];
#pragma unroll
    for (int i = 0; i < 4; i++) ys[i] = g_qh[(2 * r) * 12288 + t * 4096 + b * 128 + lane + 32 * i];
#pragma unroll
    for (int i = 4; i < 8; i++) ys[i] = g_qh[(2 * r + 1) * 12288 + (2 - t) * 4096 + b * 128 + lane + 32 * (i - 4)];
    for (int o = 0; o < 25; o++) {
        float acc = 0.f;
#pragma unroll
        for (int i = 0; i < 8; i++) acc = fmaf(ys[i], __ldg(&W[o * 256 + lane + 32 * i]), acc);
#pragma unroll
        for (int off = 16; off; off >>= 1) acc += __shfl_xor_sync(0xffffffffu, acc, off);
        if (lane == 0) z[wy][o] = acc + bias[o];
    }
    __syncwarp();
    if (lane < 25) {
        float mx = -1e30f;
#pragma unroll
        for (int o = 0; o < 25; o++) mx = fmaxf(mx, z[wy][o]);
        float sm = 0.f;
#pragma unroll
        for (int o = 0; o < 25; o++) sm += expf(z[wy][o] - mx);
        g_qattn[t * 2400 + lane * 96 + r * 32 + b] = expf(z[wy][lane] - mx) / sm;
    }
}

// ---------------- propagation (R,B fused into 96 lanes) ----------------
__global__ void k_zero_state() {
    int i = blockIdx.x * 256 + threadIdx.x;
    if (i < NN * 24) {
        ((float4*)g_mem)[i] = make_float4(0.f, 0.f, 0.f, 0.f);
        ((float4*)g_next)[i] = make_float4(0.f, 0.f, 0.f, 0.f);
    }
}
__global__ void k_set_heads(const int* __restrict__ heads) {
    int i = threadIdx.x;  // 96
    if (i < 96) g_mem[heads[i & 31] * 96 + i] = 1.0f;
}
__global__ void k_zero_sums() {
    if (threadIdx.x < 96) g_sums[threadIdx.x] = 0.f;
}
// thread handles one (edge, quad-of-4-cols); atomics predicated on nonzero memory
__global__ void __launch_bounds__(256) k_scatter(const int* __restrict__ rels,
                                                 const int* __restrict__ th,
                                                 const int* __restrict__ tt, int tstep) {
    __shared__ float qs[25 * 96];
    for (int i = threadIdx.x; i < 2400; i += 256) qs[i] = g_qattn[tstep * 2400 + i];
    __syncthreads();
    int i = blockIdx.x * 256 + threadIdx.x;  // exactly E*24 threads
    int e = i / 24, q = i - e * 24, c0 = q * 4;
    int h = __ldg(&th[e]), t_ = __ldg(&tt[e]);
    float4 mh = *reinterpret_cast<const float4*>(&g_mem[h * 96 + c0]);
    float4 mt = *reinterpret_cast<const float4*>(&g_mem[t_ * 96 + c0]);
    // one-hot start => vast majority of edges see all-zero memory on both ends
    bool any_h = (mh.x != 0.f) | (mh.y != 0.f) | (mh.z != 0.f) | (mh.w != 0.f);
    bool any_t = (mt.x != 0.f) | (mt.y != 0.f) | (mt.z != 0.f) | (mt.w != 0.f);
    if (!(any_h | any_t)) return;
    int rel = __ldg(&rels[e]);
    float wv = __ldg(&g_eattn[h * 24 + rel]);
    const float* qf = qs + rel * 96 + c0;
    const float* qr = qs + (rel + 12) * 96 + c0;
    float* nt = g_next + t_ * 96 + c0;
    float* nh = g_next + h * 96 + c0;
    if (mh.x != 0.f) atomicAdd(nt + 0, qf[0] * wv * mh.x);
    if (mh.y != 0.f) atomicAdd(nt + 1, qf[1] * wv * mh.y);
    if (mh.z != 0.f) atomicAdd(nt + 2, qf[2] * wv * mh.z);
    if (mh.w != 0.f) atomicAdd(nt + 3, qf[3] * wv * mh.w);
    if (mt.x != 0.f) atomicAdd(nh + 0, qr[0] * wv * mt.x);
    if (mt.y != 0.f) atomicAdd(nh + 1, qr[1] * wv * mt.y);
    if (mt.z != 0.f) atomicAdd(nh + 2, qr[2] * wv * mt.z);
    if (mt.w != 0.f) atomicAdd(nh + 3, qr[3] * wv * mt.w);
}
// add self term, accumulate per-column sums (one atomic per thread)
__global__ void k_selfsum(int tstep) {
    int col = threadIdx.x;  // 96
    float qself = g_qattn[tstep * 2400 + 24 * 96 + col];
    int nbase = blockIdx.x * 64;
    float acc = 0.f;
    for (int r2 = 0; r2 < 64; r2++) {
        int n = nbase + r2;
        if (n < NN) {
            int idx = n * 96 + col;
            float v = g_next[idx] + g_mem[idx] * qself;
            g_next[idx] = v;
            acc += v;
        }
    }
    atomicAdd(&g_sums[col], acc);
}
__global__ void k_norm() {
    __shared__ float rs[96];
    if (threadIdx.x < 96) rs[threadIdx.x] = 1.0f / fmaxf(1e-20f, g_sums[threadIdx.x]);
    __syncthreads();
    int i = blockIdx.x * 256 + threadIdx.x;
    if (i >= NN * 96) return;
    int col = i % 96;
    g_mem[i] = g_next[i] * rs[col];
    g_next[i] = 0.f;
}
__global__ void k_final(float* __restrict__ out) {
    int i = blockIdx.x * 256 + threadIdx.x;
    if (i >= BB * NN) return;
    int b = i / NN, n = i - b * NN;
    out[i] = g_mem[n * 96 + b] + g_mem[n * 96 + 32 + b] + g_mem[n * 96 + 64 + b];
}

// ---------------- launcher ----------------
extern "C" void kernel_launch(void* const* d_in, const int* in_sizes, int n_in,
                              void* d_out, int out_size) {
    const int* queries = (const int*)d_in[0];
    const int* heads = (const int*)d_in[1];
    const int* rels = (const int*)d_in[2];
    const int* t_heads = (const int*)d_in[3];
    const int* t_tails = (const int*)d_in[4];
    const int* deg = (const int*)d_in[5];
    const float* qemb = (const float*)d_in[6];
    const float* eemb = (const float*)d_in[7];
    const float* q_Wih = (const float*)d_in[8];
    const float* q_Whh = (const float*)d_in[9];
    const float* q_bih = (const float*)d_in[10];
    const float* q_bhh = (const float*)d_in[11];
    const float* e_Wih = (const float*)d_in[12];
    const float* e_Whh = (const float*)d_in[13];
    const float* e_bih = (const float*)d_in[14];
    const float* e_bhh = (const float*)d_in[15];
    const float* q_lin_W = (const float*)d_in[16];
    const float* q_lin_b = (const float*)d_in[17];
    const float* e_lin_W = (const float*)d_in[18];
    const float* e_lin_b = (const float*)d_in[19];
    float* out = (float*)d_out;

    // pack weights  (launch order keeps k_elstm at index 3 = the ncu sample slot)
    k_pack_ewhh<<<(2 * 16384 + 255) / 256, 256>>>(e_Whh);                  // 0
    k_pack_exp<<<(2 * 25 * 128 + 255) / 256, 256>>>(eemb, e_Wih, e_bih, e_bhh);  // 1
    k_pack_q<<<(12 * 16384 + 768 + 255) / 256, 256>>>(q_Wih, q_Whh, q_bih, q_bhh);  // 2

    // entity path
    k_elstm<<<dim3((NN + 31) / 32, 2), 256>>>(deg);                        // 3
    k_eattn<<<(NN + 7) / 8, 256>>>(e_lin_W, e_lin_b);                      // 4

    // query path
    k_qlstm<<<6, 256>>>(queries, qemb);                                    // 5
    k_qattn<<<36, 256>>>(q_lin_W, q_lin_b);                                // 6

    // propagation: R and B fused into 96 columns, T=3 passes
    k_zero_state<<<(NN * 24 + 255) / 256, 256>>>();
    k_set_heads<<<1, 96>>>(heads);
    for (int t = 0; t < 3; t++) {
        k_zero_sums<<<1, 96>>>();
        k_scatter<<<(EE * 24) / 256, 256>>>(rels, t_heads, t_tails, t);
        k_selfsum<<<(NN + 63) / 64, 96>>>(t);
        k_norm<<<(NN * 96 + 255) / 256, 256>>>();
    }
    k_final<<<(BB * NN + 255) / 256, 256>>>(out);
}